// round 9
// baseline (speedup 1.0000x reference)
#include <cuda_runtime.h>

#define NN 100000
#define NE 1200000
#define DD 64
#define NBLK 391          // ceil(NN/256)
#define GRID_FUSED 3125   // NN/32 exact
#define OFFMASK 0x1FFFFFu
#define WSTRIDE 68        // padded row stride (floats), 272B: 16B-aligned, bank-shift 4
#define EDGE_CAP 2048

typedef unsigned long long ull;

// scratch (__device__ globals per allocation rules; zero-initialized at load)
__device__ int      g_count[NN];
__device__ unsigned g_offcnt[NN];    // off | (cnt<<21)
__device__ int      g_rank[NE];      // per-edge rank within its dst node
__device__ ull      g_edata[NE];     // packed {w_bits, src}
__device__ int      g_total;

// ---- f32x2 helpers (sm_103a packed fp32) ----
__device__ __forceinline__ ull pk(float lo, float hi) {
    ull r; asm("mov.b64 %0, {%1, %2};" : "=l"(r) : "f"(lo), "f"(hi)); return r;
}
__device__ __forceinline__ void unpk(float& lo, float& hi, ull v) {
    asm("mov.b64 {%0, %1}, %2;" : "=f"(lo), "=f"(hi) : "l"(v));
}
__device__ __forceinline__ void fma2(ull& d, ull a, ull b) {
    asm("fma.rn.f32x2 %0, %1, %2, %0;" : "+l"(d) : "l"(a), "l"(b));
}
__device__ __forceinline__ ull mul2(ull a, ull b) {
    ull r; asm("mul.rn.f32x2 %0, %1, %2;" : "=l"(r) : "l"(a), "l"(b)); return r;
}

// Launch 1: histogram + per-edge rank; resets g_total for this call.
__global__ void __launch_bounds__(256) hist_kernel(const int* __restrict__ dst) {
    unsigned g = blockIdx.x * 256u + threadIdx.x;
    if (g == 0) g_total = 0;
    if (g >= NE / 4) return;
    int4 d = __ldg(reinterpret_cast<const int4*>(dst) + g);
    int4 r;
    r.x = atomicAdd(&g_count[d.x], 1);
    r.y = atomicAdd(&g_count[d.y], 1);
    r.z = atomicAdd(&g_count[d.z], 1);
    r.w = atomicAdd(&g_count[d.w], 1);
    reinterpret_cast<int4*>(g_rank)[g] = r;
}

// Launch 2: block-local scan + one global atomicAdd base; packed off|cnt;
// re-zeros g_count (graph-replay invariant).
__global__ void __launch_bounds__(256) offsets_kernel() {
    __shared__ int arr[256];
    __shared__ int sBase;
    int t = threadIdx.x;
    int i = blockIdx.x * 256 + t;
    int c = (i < NN) ? g_count[i] : 0;
    arr[t] = c;
    __syncthreads();
    #pragma unroll
    for (int off = 1; off < 256; off <<= 1) {
        int v = (t >= off) ? arr[t - off] : 0;
        __syncthreads();
        arr[t] += v;
        __syncthreads();
    }
    if (t == 255) sBase = atomicAdd(&g_total, arr[255]);
    __syncthreads();
    if (i < NN) {
        g_offcnt[i] = (unsigned)(sBase + arr[t] - c) | ((unsigned)c << 21);
        g_count[i] = 0;
    }
}

// Launch 3: atomic-free fill. pos = off(dst) + rank. 4 edges/thread.
__global__ void __launch_bounds__(256) fill_kernel(
    const int* __restrict__ src, const int* __restrict__ dst,
    const float* __restrict__ ew, const float* __restrict__ em) {
    unsigned g = blockIdx.x * 256u + threadIdx.x;
    if (g >= NE / 4) return;
    int4   s = __ldg(reinterpret_cast<const int4*>(src) + g);
    int4   d = __ldg(reinterpret_cast<const int4*>(dst) + g);
    int4   r = reinterpret_cast<const int4*>(g_rank)[g];
    float4 w = __ldg(reinterpret_cast<const float4*>(ew) + g);
    float4 m = __ldg(reinterpret_cast<const float4*>(em) + g);
    int p0 = (int)(g_offcnt[d.x] & OFFMASK) + r.x;
    int p1 = (int)(g_offcnt[d.y] & OFFMASK) + r.y;
    int p2 = (int)(g_offcnt[d.z] & OFFMASK) + r.z;
    int p3 = (int)(g_offcnt[d.w] & OFFMASK) + r.w;
    g_edata[p0] = ((ull)(unsigned)__float_as_int(w.x * m.x) << 32) | (unsigned)s.x;
    g_edata[p1] = ((ull)(unsigned)__float_as_int(w.y * m.y) << 32) | (unsigned)s.y;
    g_edata[p2] = ((ull)(unsigned)__float_as_int(w.z * m.z) << 32) | (unsigned)s.z;
    g_edata[p3] = ((ull)(unsigned)__float_as_int(w.w * m.w) << 32) | (unsigned)s.w;
}

// Launch 4: fused gather-mean + dual GEMM. 32 nodes/block, 256 threads.
// Dyn smem (floats): sWs[64*68] | sWn[64*68] | sAT2[64*68] | sBT2[64*68] | sEdge[2048 ull]
// sAT2/sBT2 hold node-DUPLICATED k-major values: [k][2n]=[k][2n+1]=x[n][k],
// so a ulonglong2 load yields pre-splatted (a,a) f32x2 operands (no MOVs).
__global__ void __launch_bounds__(256) fused_kernel(
    const float* __restrict__ feat,
    const float* __restrict__ Ws, const float* __restrict__ bs,
    const float* __restrict__ Wn, const float* __restrict__ bn,
    float* __restrict__ out) {
    extern __shared__ float smem[];
    float* sWs  = smem;
    float* sWn  = smem + 4352;
    float* sAT2 = smem + 8704;
    float* sBT2 = smem + 13056;
    ull*   sEdge = reinterpret_cast<ull*>(smem + 17408);

    int t = threadIdx.x;
    int base = blockIdx.x * 32;   // 3125*32 = 100000 exact

    // W fill, k-major: W[j][k] -> sW[k*68 + j]
    for (int i = t; i < DD * DD; i += 256) {
        int j = i >> 6, k = i & 63;
        sWs[k * WSTRIDE + j] = Ws[i];
        sWn[k * WSTRIDE + j] = Wn[i];
    }

    // stage self feat rows, transposed + node-duplicated
    for (int i = t; i < 32 * 16; i += 256) {
        int n = i >> 4, c = i & 15;
        float4 f = __ldg(reinterpret_cast<const float4*>(feat) + (size_t)(base + n) * 16 + c);
        int k0 = c * 4;
        ull* p = reinterpret_cast<ull*>(sAT2);
        // float index (k*68 + 2n) is even -> ull index (k*34 + n)
        p[(k0 + 0) * 34 + n] = pk(f.x, f.x);
        p[(k0 + 1) * 34 + n] = pk(f.y, f.y);
        p[(k0 + 2) * 34 + n] = pk(f.z, f.z);
        p[(k0 + 3) * 34 + n] = pk(f.w, f.w);
    }

    // stage this block's contiguous CSR edge range
    unsigned oc0 = g_offcnt[base];
    unsigned ocL = g_offcnt[base + 31];
    int blockBeg = (int)(oc0 & OFFMASK);
    int total = (int)(ocL & OFFMASK) + (int)(ocL >> 21) - blockBeg;
    bool fits = (total <= EDGE_CAP);
    if (fits) {
        for (int i = t; i < total; i += 256)
            sEdge[i] = g_edata[blockBeg + i];
    }
    __syncthreads();

    // Phase A: gather. 8 threads/node; per-thread chains, unroll 4.
    {
        int nl = t >> 3;          // local node 0..31
        int l8 = t & 7;
        unsigned oc = g_offcnt[base + nl];
        int beg = (int)(oc & OFFMASK);
        int cnt = (int)(oc >> 21);
        ull a0x = 0, a0y = 0, a1x = 0, a1y = 0;
        const ulonglong2* f16 = reinterpret_cast<const ulonglong2*>(feat);
        if (fits) {
            const ull* ep = sEdge + (beg - blockBeg);
            #pragma unroll 4
            for (int i2 = 0; i2 < cnt; i2++) {
                ull ed = ep[i2];
                int s = (int)(unsigned)(ed & 0xffffffffull);
                float wgt = __int_as_float((int)(ed >> 32));
                ull w2 = pk(wgt, wgt);
                ulonglong2 f0 = __ldg(f16 + (size_t)s * 16 + l8);
                ulonglong2 f1 = __ldg(f16 + (size_t)s * 16 + 8 + l8);
                fma2(a0x, f0.x, w2); fma2(a0y, f0.y, w2);
                fma2(a1x, f1.x, w2); fma2(a1y, f1.y, w2);
            }
        } else {
            #pragma unroll 4
            for (int i2 = 0; i2 < cnt; i2++) {
                ull ed = __ldg((const ull*)g_edata + beg + i2);
                int s = (int)(unsigned)(ed & 0xffffffffull);
                float wgt = __int_as_float((int)(ed >> 32));
                ull w2 = pk(wgt, wgt);
                ulonglong2 f0 = __ldg(f16 + (size_t)s * 16 + l8);
                ulonglong2 f1 = __ldg(f16 + (size_t)s * 16 + 8 + l8);
                fma2(a0x, f0.x, w2); fma2(a0y, f0.y, w2);
                fma2(a1x, f1.x, w2); fma2(a1y, f1.y, w2);
            }
        }
        float inv = 1.0f / fmaxf((float)cnt, 1.0f);
        ull iv = pk(inv, inv);
        a0x = mul2(a0x, iv); a0y = mul2(a0y, iv);
        a1x = mul2(a1x, iv); a1y = mul2(a1y, iv);
        // store transposed + duplicated: chunk l8 -> k=4*l8.., chunk 8+l8 -> k=32+4*l8..
        ull* p = reinterpret_cast<ull*>(sBT2);
        float v0, v1;
        int k0 = 4 * l8;
        unpk(v0, v1, a0x); p[(k0 + 0) * 34 + nl] = pk(v0, v0); p[(k0 + 1) * 34 + nl] = pk(v1, v1);
        unpk(v0, v1, a0y); p[(k0 + 2) * 34 + nl] = pk(v0, v0); p[(k0 + 3) * 34 + nl] = pk(v1, v1);
        int k1 = 32 + 4 * l8;
        unpk(v0, v1, a1x); p[(k1 + 0) * 34 + nl] = pk(v0, v0); p[(k1 + 1) * 34 + nl] = pk(v1, v1);
        unpk(v0, v1, a1y); p[(k1 + 2) * 34 + nl] = pk(v0, v0); p[(k1 + 3) * 34 + nl] = pk(v1, v1);
    }
    __syncthreads();

    // Phase B: dual GEMM, FFMA2, no splats. jg warp-uniform (2/warp).
    int jg = t >> 4;     // col group 0..15: cols 4jg..4jg+3
    int nt = t & 15;     // node pair: local nodes 2nt, 2nt+1
    int j0 = jg * 4;

    ull bias01 = pk(__ldg(bs + j0 + 0) + __ldg(bn + j0 + 0),
                    __ldg(bs + j0 + 1) + __ldg(bn + j0 + 1));
    ull bias23 = pk(__ldg(bs + j0 + 2) + __ldg(bn + j0 + 2),
                    __ldg(bs + j0 + 3) + __ldg(bn + j0 + 3));
    ull acc0_01 = bias01, acc0_23 = bias23;   // node 2nt
    ull acc1_01 = bias01, acc1_23 = bias23;   // node 2nt+1

    const ulonglong2* pW = reinterpret_cast<const ulonglong2*>(sWs + j0);
    const ulonglong2* pU = reinterpret_cast<const ulonglong2*>(sWn + j0);
    const ulonglong2* pA = reinterpret_cast<const ulonglong2*>(sAT2 + 4 * nt);
    const ulonglong2* pB = reinterpret_cast<const ulonglong2*>(sBT2 + 4 * nt);

    #pragma unroll 8
    for (int k = 0; k < 64; k++) {
        // row stride 68 floats = 17 ulonglong2
        ulonglong2 w = pW[k * 17];    // (w_j0,w_j0+1),(w_j0+2,w_j0+3)
        ulonglong2 u = pU[k * 17];
        ulonglong2 a = pA[k * 17];    // (a0,a0),(a1,a1) pre-splatted
        ulonglong2 b = pB[k * 17];
        fma2(acc0_01, a.x, w.x); fma2(acc0_23, a.x, w.y);
        fma2(acc1_01, a.y, w.x); fma2(acc1_23, a.y, w.y);
        fma2(acc0_01, b.x, u.x); fma2(acc0_23, b.x, u.y);
        fma2(acc1_01, b.y, u.x); fma2(acc1_23, b.y, u.y);
    }

    int n0 = base + 2 * nt;
    float4 o;
    unpk(o.x, o.y, acc0_01); unpk(o.z, o.w, acc0_23);
    reinterpret_cast<float4*>(out)[(size_t)n0 * 16 + jg] = o;
    unpk(o.x, o.y, acc1_01); unpk(o.z, o.w, acc1_23);
    reinterpret_cast<float4*>(out)[(size_t)(n0 + 1) * 16 + jg] = o;
}

extern "C" void kernel_launch(void* const* d_in, const int* in_sizes, int n_in,
                              void* d_out, int out_size) {
    const float* feat = (const float*)d_in[0];
    const int*   src  = (const int*)d_in[1];
    const int*   dst  = (const int*)d_in[2];
    const float* ew   = (const float*)d_in[3];
    const float* em   = (const float*)d_in[4];
    const float* Ws   = (const float*)d_in[5];
    const float* bs   = (const float*)d_in[6];
    const float* Wn   = (const float*)d_in[7];
    const float* bn   = (const float*)d_in[8];
    float* out = (float*)d_out;

    const int smem_bytes = (17408 + EDGE_CAP * 2) * 4;   // 86016
    cudaFuncSetAttribute(fused_kernel,
                         cudaFuncAttributeMaxDynamicSharedMemorySize, smem_bytes);

    hist_kernel<<<1172, 256>>>(dst);                 // NE/4 threads
    offsets_kernel<<<NBLK, 256>>>();
    fill_kernel<<<1172, 256>>>(src, dst, ew, em);
    fused_kernel<<<GRID_FUSED, 256, smem_bytes>>>(feat, Ws, bs, Wn, bn, out);
}

// round 11
// speedup vs baseline: 1.3534x; 1.3534x over previous
#include <cuda_runtime.h>

#define NN 100000
#define NE 1200000
#define DD 64
#define NBLK 391          // ceil(NN/256)
#define OFFMASK 0x1FFFFFu
#define GTILE 128
#define GGRID 782         // ceil(NN/128)
#define WROW 68           // W smem row stride (floats)
#define ATROW 132         // A/B smem row stride (floats)

typedef unsigned long long ull;

// scratch (__device__ globals per allocation rules; zero-initialized at load)
__device__ int      g_count[NN];
__device__ unsigned g_offcnt[NN];    // off | (cnt<<21)
__device__ int      g_rank[NE];      // per-edge rank within its dst node
__device__ ull      g_edata[NE];     // packed {w_bits, src}
__device__ float    g_neigh[NN * DD];
__device__ int      g_total;

// ---- f32x2 helpers ----
__device__ __forceinline__ ull pk(float lo, float hi) {
    ull r; asm("mov.b64 %0, {%1, %2};" : "=l"(r) : "f"(lo), "f"(hi)); return r;
}
__device__ __forceinline__ void unpk(float& lo, float& hi, ull v) {
    asm("mov.b64 {%0, %1}, %2;" : "=f"(lo), "=f"(hi) : "l"(v));
}
__device__ __forceinline__ void fma2(ull& d, ull a, ull b) {
    asm("fma.rn.f32x2 %0, %1, %2, %0;" : "+l"(d) : "l"(a), "l"(b));
}
__device__ __forceinline__ ull mul2(ull a, ull b) {
    ull r; asm("mul.rn.f32x2 %0, %1, %2;" : "=l"(r) : "l"(a), "l"(b)); return r;
}

// Launch 1: histogram + per-edge rank; resets g_total for this call.
__global__ void __launch_bounds__(256) hist_kernel(const int* __restrict__ dst) {
    unsigned g = blockIdx.x * 256u + threadIdx.x;
    if (g == 0) g_total = 0;
    if (g >= NE / 4) return;
    int4 d = __ldg(reinterpret_cast<const int4*>(dst) + g);
    int4 r;
    r.x = atomicAdd(&g_count[d.x], 1);
    r.y = atomicAdd(&g_count[d.y], 1);
    r.z = atomicAdd(&g_count[d.z], 1);
    r.w = atomicAdd(&g_count[d.w], 1);
    reinterpret_cast<int4*>(g_rank)[g] = r;
}

// Launch 2: block-local scan + single atomic base; re-zeros g_count.
__global__ void __launch_bounds__(256) offsets_kernel() {
    __shared__ int arr[256];
    __shared__ int sBase;
    int t = threadIdx.x;
    int i = blockIdx.x * 256 + t;
    int c = (i < NN) ? g_count[i] : 0;
    arr[t] = c;
    __syncthreads();
    #pragma unroll
    for (int off = 1; off < 256; off <<= 1) {
        int v = (t >= off) ? arr[t - off] : 0;
        __syncthreads();
        arr[t] += v;
        __syncthreads();
    }
    if (t == 255) sBase = atomicAdd(&g_total, arr[255]);
    __syncthreads();
    if (i < NN) {
        g_offcnt[i] = (unsigned)(sBase + arr[t] - c) | ((unsigned)c << 21);
        g_count[i] = 0;
    }
}

// Launch 3: atomic-free CSR fill. pos = off(dst) + rank. 4 edges/thread.
__global__ void __launch_bounds__(256) fill_kernel(
    const int* __restrict__ src, const int* __restrict__ dst,
    const float* __restrict__ ew, const float* __restrict__ em) {
    unsigned g = blockIdx.x * 256u + threadIdx.x;
    if (g >= NE / 4) return;
    int4   s = __ldg(reinterpret_cast<const int4*>(src) + g);
    int4   d = __ldg(reinterpret_cast<const int4*>(dst) + g);
    int4   r = reinterpret_cast<const int4*>(g_rank)[g];
    float4 w = __ldg(reinterpret_cast<const float4*>(ew) + g);
    float4 m = __ldg(reinterpret_cast<const float4*>(em) + g);
    int p0 = (int)(g_offcnt[d.x] & OFFMASK) + r.x;
    int p1 = (int)(g_offcnt[d.y] & OFFMASK) + r.y;
    int p2 = (int)(g_offcnt[d.z] & OFFMASK) + r.z;
    int p3 = (int)(g_offcnt[d.w] & OFFMASK) + r.w;
    g_edata[p0] = ((ull)(unsigned)__float_as_int(w.x * m.x) << 32) | (unsigned)s.x;
    g_edata[p1] = ((ull)(unsigned)__float_as_int(w.y * m.y) << 32) | (unsigned)s.y;
    g_edata[p2] = ((ull)(unsigned)__float_as_int(w.z * m.z) << 32) | (unsigned)s.z;
    g_edata[p3] = ((ull)(unsigned)__float_as_int(w.w * m.w) << 32) | (unsigned)s.w;
}

// Launch 4: gather-mean only, high occupancy (no big smem). 8 threads/node,
// 32 nodes/block. Writes mean rows to g_neigh.
__global__ void __launch_bounds__(256) gather_kernel(const float* __restrict__ feat) {
    int t = threadIdx.x;
    int nl = t >> 3;
    int l8 = t & 7;
    int node = blockIdx.x * 32 + nl;     // 3125*32 = 100000 exact
    unsigned oc = g_offcnt[node];
    int beg = (int)(oc & OFFMASK);
    int cnt = (int)(oc >> 21);
    ull a0x = 0, a0y = 0, a1x = 0, a1y = 0;
    const ulonglong2* f16 = reinterpret_cast<const ulonglong2*>(feat);
    #pragma unroll 4
    for (int i2 = 0; i2 < cnt; i2++) {
        ull ed = __ldg((const ull*)g_edata + beg + i2);
        int s = (int)(unsigned)(ed & 0xffffffffull);
        float wgt = __int_as_float((int)(ed >> 32));
        ull w2 = pk(wgt, wgt);
        ulonglong2 f0 = __ldg(f16 + (size_t)s * 16 + l8);       // floats 4l8..4l8+3
        ulonglong2 f1 = __ldg(f16 + (size_t)s * 16 + 8 + l8);   // floats 32+4l8..
        fma2(a0x, f0.x, w2); fma2(a0y, f0.y, w2);
        fma2(a1x, f1.x, w2); fma2(a1y, f1.y, w2);
    }
    float inv = 1.0f / fmaxf((float)cnt, 1.0f);
    ull iv = pk(inv, inv);
    a0x = mul2(a0x, iv); a0y = mul2(a0y, iv);
    a1x = mul2(a1x, iv); a1y = mul2(a1y, iv);
    float4 o;
    unpk(o.x, o.y, a0x); unpk(o.z, o.w, a0y);
    reinterpret_cast<float4*>(g_neigh)[(size_t)node * 16 + l8] = o;
    unpk(o.x, o.y, a1x); unpk(o.z, o.w, a1y);
    reinterpret_cast<float4*>(g_neigh)[(size_t)node * 16 + 8 + l8] = o;
}

// Launch 5: dense dual GEMM, fma-bound. 128 nodes/block, 256 threads,
// thread tile = 4 nodes x 8 cols (16 f32x2 accs). 100KB dyn smem.
__global__ void __launch_bounds__(256) gemm_kernel(
    const float* __restrict__ feat,
    const float* __restrict__ Ws, const float* __restrict__ bs,
    const float* __restrict__ Wn, const float* __restrict__ bn,
    float* __restrict__ out) {
    extern __shared__ float sm[];
    float* sWs = sm;                     // 64*68  = 4352 floats
    float* sWn = sm + 4352;              // 4352
    float* sAT = sm + 8704;              // 64*132 = 8448
    float* sBT = sm + 17152;             // 8448   -> total 25600 fl = 100KB

    int t = threadIdx.x;
    int base = blockIdx.x * GTILE;

    // W k-major: sW[k*WROW + j] = W[j][k]; coalesced global reads.
    for (int i = t; i < DD * DD; i += 256) {
        int j = i >> 6, k = i & 63;
        sWs[k * WROW + j] = Ws[i];
        sWn[k * WROW + j] = Wn[i];
    }
    // A/B transposed k-major: sAT[k*ATROW + n] = x[base+n][k]
    for (int i = t; i < GTILE * 16; i += 256) {
        int n = i >> 4, c = i & 15;
        int node = base + n;
        float4 f = make_float4(0.f, 0.f, 0.f, 0.f);
        float4 h = make_float4(0.f, 0.f, 0.f, 0.f);
        if (node < NN) {
            f = __ldg(reinterpret_cast<const float4*>(feat) + (size_t)node * 16 + c);
            h = reinterpret_cast<const float4*>(g_neigh)[(size_t)node * 16 + c];
        }
        int k0 = 4 * c;
        sAT[(k0 + 0) * ATROW + n] = f.x;
        sAT[(k0 + 1) * ATROW + n] = f.y;
        sAT[(k0 + 2) * ATROW + n] = f.z;
        sAT[(k0 + 3) * ATROW + n] = f.w;
        sBT[(k0 + 0) * ATROW + n] = h.x;
        sBT[(k0 + 1) * ATROW + n] = h.y;
        sBT[(k0 + 2) * ATROW + n] = h.z;
        sBT[(k0 + 3) * ATROW + n] = h.w;
    }
    __syncthreads();

    int jg = t & 7;      // cols 8jg..8jg+7
    int ng = t >> 3;     // nodes 4ng..4ng+3
    int j0 = 8 * jg, n0 = 4 * ng;

    ull bias[4];
    #pragma unroll
    for (int p = 0; p < 4; p++)
        bias[p] = pk(__ldg(bs + j0 + 2 * p)     + __ldg(bn + j0 + 2 * p),
                     __ldg(bs + j0 + 2 * p + 1) + __ldg(bn + j0 + 2 * p + 1));
    ull acc[4][4];       // [node][colpair], lanes = (col j0+2p, j0+2p+1)
    #pragma unroll
    for (int n = 0; n < 4; n++)
        #pragma unroll
        for (int p = 0; p < 4; p++) acc[n][p] = bias[p];

    const float* pW = sWs + j0;
    const float* pU = sWn + j0;
    const float* pA = sAT + n0;
    const float* pB = sBT + n0;

    #pragma unroll 4
    for (int k = 0; k < 64; k++) {
        ulonglong2 w01 = *reinterpret_cast<const ulonglong2*>(pW + k * WROW);
        ulonglong2 w23 = *reinterpret_cast<const ulonglong2*>(pW + k * WROW + 4);
        ulonglong2 u01 = *reinterpret_cast<const ulonglong2*>(pU + k * WROW);
        ulonglong2 u23 = *reinterpret_cast<const ulonglong2*>(pU + k * WROW + 4);
        float4 a = *reinterpret_cast<const float4*>(pA + k * ATROW);
        float4 b = *reinterpret_cast<const float4*>(pB + k * ATROW);
        ull as0 = pk(a.x, a.x), as1 = pk(a.y, a.y), as2 = pk(a.z, a.z), as3 = pk(a.w, a.w);
        ull bs0 = pk(b.x, b.x), bs1 = pk(b.y, b.y), bs2 = pk(b.z, b.z), bs3 = pk(b.w, b.w);
        fma2(acc[0][0], as0, w01.x); fma2(acc[0][1], as0, w01.y);
        fma2(acc[0][2], as0, w23.x); fma2(acc[0][3], as0, w23.y);
        fma2(acc[1][0], as1, w01.x); fma2(acc[1][1], as1, w01.y);
        fma2(acc[1][2], as1, w23.x); fma2(acc[1][3], as1, w23.y);
        fma2(acc[2][0], as2, w01.x); fma2(acc[2][1], as2, w01.y);
        fma2(acc[2][2], as2, w23.x); fma2(acc[2][3], as2, w23.y);
        fma2(acc[3][0], as3, w01.x); fma2(acc[3][1], as3, w01.y);
        fma2(acc[3][2], as3, w23.x); fma2(acc[3][3], as3, w23.y);
        fma2(acc[0][0], bs0, u01.x); fma2(acc[0][1], bs0, u01.y);
        fma2(acc[0][2], bs0, u23.x); fma2(acc[0][3], bs0, u23.y);
        fma2(acc[1][0], bs1, u01.x); fma2(acc[1][1], bs1, u01.y);
        fma2(acc[1][2], bs1, u23.x); fma2(acc[1][3], bs1, u23.y);
        fma2(acc[2][0], bs2, u01.x); fma2(acc[2][1], bs2, u01.y);
        fma2(acc[2][2], bs2, u23.x); fma2(acc[2][3], bs2, u23.y);
        fma2(acc[3][0], bs3, u01.x); fma2(acc[3][1], bs3, u01.y);
        fma2(acc[3][2], bs3, u23.x); fma2(acc[3][3], bs3, u23.y);
    }

    #pragma unroll
    for (int n = 0; n < 4; n++) {
        int node = base + n0 + n;
        if (node < NN) {
            float4 o;
            unpk(o.x, o.y, acc[n][0]); unpk(o.z, o.w, acc[n][1]);
            reinterpret_cast<float4*>(out)[(size_t)node * 16 + 2 * jg] = o;
            unpk(o.x, o.y, acc[n][2]); unpk(o.z, o.w, acc[n][3]);
            reinterpret_cast<float4*>(out)[(size_t)node * 16 + 2 * jg + 1] = o;
        }
    }
}

extern "C" void kernel_launch(void* const* d_in, const int* in_sizes, int n_in,
                              void* d_out, int out_size) {
    const float* feat = (const float*)d_in[0];
    const int*   src  = (const int*)d_in[1];
    const int*   dst  = (const int*)d_in[2];
    const float* ew   = (const float*)d_in[3];
    const float* em   = (const float*)d_in[4];
    const float* Ws   = (const float*)d_in[5];
    const float* bs   = (const float*)d_in[6];
    const float* Wn   = (const float*)d_in[7];
    const float* bn   = (const float*)d_in[8];
    float* out = (float*)d_out;

    const int gemm_smem = 25600 * 4;   // 100KB
    cudaFuncSetAttribute(gemm_kernel,
                         cudaFuncAttributeMaxDynamicSharedMemorySize, gemm_smem);

    hist_kernel<<<1172, 256>>>(dst);
    offsets_kernel<<<NBLK, 256>>>();
    fill_kernel<<<1172, 256>>>(src, dst, ew, em);
    gather_kernel<<<3125, 256>>>(feat);
    gemm_kernel<<<GGRID, 256, gemm_smem>>>(feat, Ws, bs, Wn, bn, out);
}